// round 12
// baseline (speedup 1.0000x reference)
#include <cuda_runtime.h>
#include <cuda_fp16.h>
#include <cstdint>

// Z[b,w,t] = sum_c Q[b,w,c] * ( K[b,w+t,c] + bias[c,t] ),  B=16, T=1024, C=128.
//
// Fused per-tile kernel (128x128), single-pass fp16, software-pipelined:
//  - panel c-high prefetched to regs; converted+STS'd under band ksteps 0-3 (c-low)
//  - bias gather LDGs drain under band ksteps 4-7 (c-high)
//  - band window trimmed to 144 cols/m-tile (h=0: 80, h=1: 64) - exact coverage
//  - scatter band acc -> smem zs (overlay on panel); bias GEMM; fused STG epilogue.

#define TDIM   1024
#define CDIM   128
#define KROWS  2047
#define NTHREADS 512

// ---- smem layout (bytes); fp16 buffers: rows of 256B, 16B chunks XOR-swizzled ----
#define OQ  0                            // Q fp16 (128 x 256B) = 32768
#define OPH 32768                        // K panel (256 x 256B) = 65536
#define OZS OPH                          // fp32 Z overlay (128 x ZSTRIDE x 4 = 67584)
#define ZSTRIDE 132
#define ZS_BYTES (128 * ZSTRIDE * 4)     // 67584 (region size; panel 65536 fits under it)
#define OBH (OPH + ZS_BYTES)             // bias B (128 x 256B) at 100352
#define SMEM_BYTES (OBH + 32768)         // 133120

__device__ __forceinline__ void ldsm4(uint32_t addr, uint32_t& r0, uint32_t& r1,
                                      uint32_t& r2, uint32_t& r3) {
    asm volatile("ldmatrix.sync.aligned.m8n8.x4.shared.b16 {%0,%1,%2,%3}, [%4];"
                 : "=r"(r0), "=r"(r1), "=r"(r2), "=r"(r3) : "r"(addr));
}
__device__ __forceinline__ void mma16816(float* d, uint32_t a0, uint32_t a1,
                                         uint32_t a2, uint32_t a3,
                                         uint32_t b0, uint32_t b1) {
    asm volatile("mma.sync.aligned.m16n8k16.row.col.f32.f16.f16.f32 "
                 "{%0,%1,%2,%3}, {%4,%5,%6,%7}, {%8,%9}, {%0,%1,%2,%3};"
                 : "+f"(d[0]), "+f"(d[1]), "+f"(d[2]), "+f"(d[3])
                 : "r"(a0), "r"(a1), "r"(a2), "r"(a3), "r"(b0), "r"(b1));
}
__device__ __forceinline__ uint32_t smem_u32(const void* p) {
    uint32_t a;
    asm("{ .reg .u64 t; cvta.to.shared.u64 t, %1; cvt.u32.u64 %0, t; }" : "=r"(a) : "l"(p));
    return a;
}
__device__ __forceinline__ uint32_t pack_h2(float x, float y) {
    __half2 h = __halves2half2(__float2half_rn(x), __float2half_rn(y));
    return *reinterpret_cast<uint32_t*>(&h);
}
// swizzled byte offset for (row, cv) with cv = float4 index (4 c-values -> 8B fp16)
__device__ __forceinline__ uint32_t sw_off(int row, int cv) {
    int c2 = cv >> 1;
    return (uint32_t)(row * 256 + (((c2) ^ (row & 7)) << 4) + (cv & 1) * 8);
}
// store 4 c-values as fp16 into buffer `buf`
__device__ __forceinline__ void st_s4(char* sm, int buf, int row, int cv, float4 v) {
    *reinterpret_cast<uint2*>(sm + buf + sw_off(row, cv)) =
        make_uint2(pack_h2(v.x, v.y), pack_h2(v.z, v.w));
}

__global__ __launch_bounds__(NTHREADS, 1)
void sw_fused_kernel(const float* __restrict__ Q,
                     const float* __restrict__ Km,
                     const float* __restrict__ bias,
                     float* __restrict__ Z)
{
    extern __shared__ char smem[];
    const uint32_t sb = smem_u32(smem);
    float* zs = reinterpret_cast<float*>(smem + OZS);

    const int tid  = threadIdx.x;
    const int wid  = tid >> 5;
    const int lane = tid & 31;

    const int b  = blockIdx.z;
    const int w0 = blockIdx.y * 128;
    const int t0 = blockIdx.x * 128;
    const int u0 = w0 + t0;

    const float* Qb = Q  + ((size_t)b * TDIM) * CDIM;
    const float* Kb = Km + ((size_t)b * KROWS) * CDIM;
    float* Zb = Z + ((size_t)b * TDIM + w0) * TDIM + t0;

    const uint32_t rx  = lane & 7;
    const uint32_t aC2 = lane >> 4;
    const uint32_t bC2 = (lane >> 3) & 1;
    const int er = lane >> 2;
    const int ec = (lane & 3) * 2;

    // ===== phase 0: prefetch panel c-high (rows 0..255, cv 16..31) into regs =====
    float4 preg[8];
#pragma unroll
    for (int r = 0; r < 8; r++) {
        int idx = tid + NTHREADS * r;           // 0..4095
        int row = idx >> 4;                     // 0..255
        int u = u0 + row; if (u > 2046) u = 2046;
        preg[r] = *reinterpret_cast<const float4*>(Kb + (size_t)u * CDIM + (16 + (idx & 15)) * 4);
    }

    // ===== phase 1: stage Q (fp16) =====
#pragma unroll
    for (int r = 0; r < 8; r++) {
        int idx = tid + NTHREADS * r;           // 4096 float4
        int row = idx >> 5, cv = idx & 31;
        float4 v = *reinterpret_cast<const float4*>(Qb + (size_t)(w0 + row) * CDIM + cv * 4);
        st_s4(smem, OQ, row, cv, v);
    }
    // stage panel c-low (rows 0..255, cv 0..15)
#pragma unroll
    for (int r = 0; r < 8; r++) {
        int idx = tid + NTHREADS * r;           // 4096
        int row = idx >> 4, cv = idx & 15;
        int u = u0 + row; if (u > 2046) u = 2046;
        float4 v = *reinterpret_cast<const float4*>(Kb + (size_t)u * CDIM + cv * 4);
        st_s4(smem, OPH, row, cv, v);
    }
    __syncthreads();

    // ===================== band GEMM (144-col window) =====================
    {
        const int mt = wid >> 1;
        const int h  = wid & 1;
        const int im = mt * 16;
        const int ng = 5 - h;                   // h=0: 5 groups (80 cols), h=1: 4 (64 cols)
        const uint32_t aRowB = (uint32_t)((im + (lane & 15)) * 256);
        uint32_t bRowG[5];
#pragma unroll
        for (int g = 0; g < 5; g++)
            bRowG[g] = (uint32_t)((im + 80 * h + 16 * g + ((lane >> 4) << 3) + (lane & 7)) * 256);

        float acc[10][4];
#pragma unroll
        for (int n = 0; n < 10; n++)
#pragma unroll
            for (int e = 0; e < 4; e++) acc[n][e] = 0.f;

#define BAND_KSTEP(ST) do {                                                  \
        uint32_t kc = 2u * (uint32_t)(ST);                                   \
        uint32_t aoff = ((kc + aC2) ^ rx) << 4;                              \
        uint32_t boff = ((kc + bC2) ^ rx) << 4;                              \
        uint32_t a0,a1,a2,a3;                                                \
        ldsm4(sb + OQ + aRowB + aoff, a0,a1,a2,a3);                          \
        _Pragma("unroll")                                                    \
        for (int g = 0; g < 5; g++) {                                        \
            if (g < ng) {                                                    \
                uint32_t b0,b1,b2,b3;                                        \
                ldsm4(sb + OPH + bRowG[g] + boff, b0,b1,b2,b3);              \
                mma16816(acc[2*g    ], a0,a1,a2,a3, b0,b1);                  \
                mma16816(acc[2*g + 1], a0,a1,a2,a3, b2,b3);                  \
            }                                                                \
        }                                                                    \
} while (0)

        // ksteps 0..3 (c-low) with interleaved c-high convert+STS
#pragma unroll
        for (int st = 0; st < 4; st++) {
            BAND_KSTEP(st);
#pragma unroll
            for (int q = 0; q < 2; q++) {
                int r = 2 * st + q;
                int idx = tid + NTHREADS * r;
                st_s4(smem, OPH, idx >> 4, 16 + (idx & 15), preg[r]);
            }
        }
        __syncthreads();   // c-high staged before ksteps 4..7 read it

        // prefetch bias gather (drains under ksteps 4..7)
        const int btau = tid >> 2;
        const int bcb  = (tid & 3) * 32;
        float f[32];
#pragma unroll
        for (int j = 0; j < 32; j++)
            f[j] = __ldg(bias + (size_t)(bcb + j) * TDIM + t0 + btau);

        // ksteps 4..7 (c-high)
#pragma unroll
        for (int st = 4; st < 8; st++) {
            BAND_KSTEP(st);
        }
#undef BAND_KSTEP

        __syncthreads();   // all panel reads done before zs overlay is written

        // ---- scatter (pure assignment): zs[im+r, j-r] = D[r, j], j in [80h, 80h+16*ng) ----
#pragma unroll
        for (int nf = 0; nf < 10; nf++) {
            if (nf < 2 * ng) {
#pragma unroll
                for (int e = 0; e < 4; e++) {
                    int r = er + ((e & 2) ? 8 : 0);
                    int j = 80 * h + nf * 8 + ec + (e & 1);
                    int tau = j - r;
                    if ((unsigned)tau < 128u)
                        zs[(im + r) * ZSTRIDE + tau] = acc[nf][e];
                }
            }
        }

        // ---- convert bias regs -> B buffer ----
#pragma unroll
        for (int j = 0; j < 16; j++) {
            uint32_t hv = pack_h2(f[2 * j], f[2 * j + 1]);
            int c = bcb + 2 * j;
            int c2 = c >> 3;
            uint32_t off = (uint32_t)(btau * 256 + ((c2 ^ (btau & 7)) << 4) + ((c * 2) & 15));
            *reinterpret_cast<uint32_t*>(smem + OBH + off) = hv;
        }
    }
    __syncthreads();

    // ===================== bias GEMM (single pass) + fused epilogue =====================
    {
        const int wr = wid >> 2;            // 0..3
        const int wc = wid & 3;             // 0..3
        uint32_t aRow[2], bRow[2];
#pragma unroll
        for (int mt = 0; mt < 2; mt++)
            aRow[mt] = (uint32_t)((wr * 32 + mt * 16 + (lane & 15)) * 256);
#pragma unroll
        for (int p = 0; p < 2; p++)
            bRow[p] = (uint32_t)((wc * 32 + p * 16 + ((lane >> 4) << 3) + (lane & 7)) * 256);

        float acc[2][4][4];
#pragma unroll
        for (int m = 0; m < 2; m++)
#pragma unroll
            for (int n = 0; n < 4; n++)
#pragma unroll
                for (int e = 0; e < 4; e++) acc[m][n][e] = 0.f;

#pragma unroll
        for (int st = 0; st < 8; st++) {
            uint32_t kc = 2u * (uint32_t)st;
            uint32_t aoff = ((kc + aC2) ^ rx) << 4;
            uint32_t boff = ((kc + bC2) ^ rx) << 4;
            uint32_t a0,a1,a2,a3,a4,a5,a6,a7;
            uint32_t b0,b1,b2,b3,b4,b5,b6,b7;
            ldsm4(sb + OQ + aRow[0] + aoff, a0,a1,a2,a3);
            ldsm4(sb + OQ + aRow[1] + aoff, a4,a5,a6,a7);
            ldsm4(sb + OBH + bRow[0] + boff, b0,b1,b2,b3);
            ldsm4(sb + OBH + bRow[1] + boff, b4,b5,b6,b7);
            mma16816(acc[0][0], a0,a1,a2,a3, b0,b1);
            mma16816(acc[0][1], a0,a1,a2,a3, b2,b3);
            mma16816(acc[0][2], a0,a1,a2,a3, b4,b5);
            mma16816(acc[0][3], a0,a1,a2,a3, b6,b7);
            mma16816(acc[1][0], a4,a5,a6,a7, b0,b1);
            mma16816(acc[1][1], a4,a5,a6,a7, b2,b3);
            mma16816(acc[1][2], a4,a5,a6,a7, b4,b5);
            mma16816(acc[1][3], a4,a5,a6,a7, b6,b7);
        }

        // ---- epilogue: Z = zs + PB, direct STG ----
#pragma unroll
        for (int mt = 0; mt < 2; mt++)
#pragma unroll
            for (int nt = 0; nt < 4; nt++) {
                int i0  = wr * 32 + mt * 16 + er;
                int tau = wc * 32 + nt * 8 + ec;
                const float* z0 = zs + i0 * ZSTRIDE + tau;
                const float* z1 = zs + (i0 + 8) * ZSTRIDE + tau;
                *reinterpret_cast<float2*>(Zb + (size_t)i0 * TDIM + tau) =
                    make_float2(acc[mt][nt][0] + z0[0], acc[mt][nt][1] + z0[1]);
                *reinterpret_cast<float2*>(Zb + (size_t)(i0 + 8) * TDIM + tau) =
                    make_float2(acc[mt][nt][2] + z1[0], acc[mt][nt][3] + z1[1]);
            }
    }
}

extern "C" void kernel_launch(void* const* d_in, const int* in_sizes, int n_in,
                              void* d_out, int out_size)
{
    const float* Q    = (const float*)d_in[0];   // (16, 1024, 128)
    const float* Km   = (const float*)d_in[1];   // (16, 2047, 128)
    const float* bias = (const float*)d_in[2];   // (1, 1, 128, 1024)
    float* Z          = (float*)d_out;           // (16, 1024, 1024)

    cudaFuncSetAttribute(sw_fused_kernel, cudaFuncAttributeMaxDynamicSharedMemorySize, SMEM_BYTES);
    dim3 grid(TDIM / 128, TDIM / 128, 16);       // (8, 8, 16) = 1024 CTAs
    sw_fused_kernel<<<grid, NTHREADS, SMEM_BYTES>>>(Q, Km, bias, Z);
}

// round 13
// speedup vs baseline: 1.0961x; 1.0961x over previous
#include <cuda_runtime.h>
#include <cuda_fp16.h>
#include <cstdint>

// Z[b,w,t] = sum_c Q[b,w,c] * ( K[b,w+t,c] + bias[c,t] ),  B=16, T=1024, C=128.
//
// Pre-pass 1: Q,K -> fp16 device globals (coalesced convert).
// Pre-pass 2: bias -> fp16 transposed g_b16[t][c].
// Main kernel = R11 structure (single-pass fp16 HMMA, band 160-col window,
// smem-Z scatter overlay, fused epilogue), but staging is pure 16B LDG->STS.

#define TDIM   1024
#define CDIM   128
#define KROWS  2047
#define NTHREADS 512

#define NQ   (16 * 1024 * 128)          // 2097152
#define NK   (16 * 2047 * 128)          // 4192256
#define NB   (1024 * 128)               // 131072

static __device__ __half g_q16[NQ];     // [b][w][c]
static __device__ __half g_k16[NK];     // [b][u][c]
static __device__ __half g_b16[NB];     // [t][c]  (transposed bias)

// ---- smem layout (bytes); fp16 buffers: rows of 256B, 16B chunks XOR-swizzled ----
#define OQ  0                            // Q fp16 (128 x 256B)
#define OPH 32768                        // K panel (272 x 256B)
#define PANEL_BYTES (272 * 256)          // 69632
#define OBH (OPH + PANEL_BYTES)          // bias B (128 x 256B) = 102400
#define SMEM_BYTES (OBH + 32768)         // 135168
#define OZS OPH                          // fp32 Z overlay (128 x 132 x 4 = 67584 <= 69632)
#define ZSTRIDE 132

__device__ __forceinline__ void ldsm4(uint32_t addr, uint32_t& r0, uint32_t& r1,
                                      uint32_t& r2, uint32_t& r3) {
    asm volatile("ldmatrix.sync.aligned.m8n8.x4.shared.b16 {%0,%1,%2,%3}, [%4];"
                 : "=r"(r0), "=r"(r1), "=r"(r2), "=r"(r3) : "r"(addr));
}
__device__ __forceinline__ void mma16816(float* d, uint32_t a0, uint32_t a1,
                                         uint32_t a2, uint32_t a3,
                                         uint32_t b0, uint32_t b1) {
    asm volatile("mma.sync.aligned.m16n8k16.row.col.f32.f16.f16.f32 "
                 "{%0,%1,%2,%3}, {%4,%5,%6,%7}, {%8,%9}, {%0,%1,%2,%3};"
                 : "+f"(d[0]), "+f"(d[1]), "+f"(d[2]), "+f"(d[3])
                 : "r"(a0), "r"(a1), "r"(a2), "r"(a3), "r"(b0), "r"(b1));
}
__device__ __forceinline__ uint32_t smem_u32(const void* p) {
    uint32_t a;
    asm("{ .reg .u64 t; cvta.to.shared.u64 t, %1; cvt.u32.u64 %0, t; }" : "=r"(a) : "l"(p));
    return a;
}
__device__ __forceinline__ uint32_t pack_h2(float x, float y) {
    __half2 h = __halves2half2(__float2half_rn(x), __float2half_rn(y));
    return *reinterpret_cast<uint32_t*>(&h);
}

// ===================== pre-pass 1: Q,K -> fp16 =====================
__global__ void cvt_qk_kernel(const float* __restrict__ Q,
                              const float* __restrict__ K)
{
    const int total = (NQ + NK) / 4;                 // float4 count
    for (int i = blockIdx.x * blockDim.x + threadIdx.x; i < total;
         i += gridDim.x * blockDim.x) {
        if (i < NQ / 4) {
            float4 v = *reinterpret_cast<const float4*>(Q + 4 * (size_t)i);
            *reinterpret_cast<uint2*>(g_q16 + 4 * (size_t)i) =
                make_uint2(pack_h2(v.x, v.y), pack_h2(v.z, v.w));
        } else {
            size_t j = (size_t)(i - NQ / 4);
            float4 v = *reinterpret_cast<const float4*>(K + 4 * j);
            *reinterpret_cast<uint2*>(g_k16 + 4 * j) =
                make_uint2(pack_h2(v.x, v.y), pack_h2(v.z, v.w));
        }
    }
}

// ===================== pre-pass 2: bias transpose -> fp16 =====================
// bias[c][t] (128 x 1024 f32) -> g_b16[t][c]
__global__ void cvt_bias_kernel(const float* __restrict__ bias)
{
    __shared__ float s[32][33];
    const int t0 = blockIdx.x * 32;
    const int c0 = blockIdx.y * 32;
    const int tx = threadIdx.x & 31;
    const int ty = threadIdx.x >> 5;                 // 0..7
#pragma unroll
    for (int r = 0; r < 4; r++) {
        int cc = ty + 8 * r;
        s[cc][tx] = bias[(size_t)(c0 + cc) * TDIM + t0 + tx];
    }
    __syncthreads();
#pragma unroll
    for (int r = 0; r < 4; r++) {
        int tt = ty + 8 * r;
        g_b16[(size_t)(t0 + tt) * CDIM + c0 + tx] = __float2half_rn(s[tx][tt]);
    }
}

// ===================== main kernel =====================
__global__ __launch_bounds__(NTHREADS, 1)
void sw_fused_kernel(float* __restrict__ Z)
{
    extern __shared__ char smem[];
    const uint32_t sb = smem_u32(smem);
    float* zs = reinterpret_cast<float*>(smem + OZS);

    const int tid  = threadIdx.x;
    const int wid  = tid >> 5;
    const int lane = tid & 31;

    const int b  = blockIdx.z;
    const int w0 = blockIdx.y * 128;
    const int t0 = blockIdx.x * 128;
    const int u0 = w0 + t0;

    float* Zb = Z + ((size_t)b * TDIM + w0) * TDIM + t0;

    const uint32_t rx  = lane & 7;
    const uint32_t aC2 = lane >> 4;
    const uint32_t bC2 = (lane >> 3) & 1;
    const int er = lane >> 2;
    const int ec = (lane & 3) * 2;

    // ---- stage Q: 2048 x 16B chunks ----
#pragma unroll
    for (int r = 0; r < 4; r++) {
        int idx = tid + NTHREADS * r;
        int row = idx >> 4, c2 = idx & 15;
        uint4 v = *reinterpret_cast<const uint4*>(
            g_q16 + ((size_t)(b * TDIM + w0 + row)) * CDIM + c2 * 8);
        *reinterpret_cast<uint4*>(smem + OQ + row * 256 + ((c2 ^ (row & 7)) << 4)) = v;
    }
    // ---- stage K panel: 272 rows x 16 chunks = 4352 ----
#pragma unroll
    for (int r = 0; r < 9; r++) {
        int idx = tid + NTHREADS * r;
        if (idx < 4352) {
            int row = idx >> 4, c2 = idx & 15;
            int u = u0 + row;
            if (u > 2046) u = 2046;              // clamped rows feed discarded taus only
            uint4 v = *reinterpret_cast<const uint4*>(
                g_k16 + ((size_t)(b * KROWS + u)) * CDIM + c2 * 8);
            *reinterpret_cast<uint4*>(smem + OPH + row * 256 + ((c2 ^ (row & 7)) << 4)) = v;
        }
    }
    // ---- stage bias: 2048 x 16B chunks (already transposed) ----
#pragma unroll
    for (int r = 0; r < 4; r++) {
        int idx = tid + NTHREADS * r;
        int row = idx >> 4, c2 = idx & 15;       // row = tau
        uint4 v = *reinterpret_cast<const uint4*>(
            g_b16 + ((size_t)(t0 + row)) * CDIM + c2 * 8);
        *reinterpret_cast<uint4*>(smem + OBH + row * 256 + ((c2 ^ (row & 7)) << 4)) = v;
    }
    __syncthreads();

    // ===================== band GEMM (single pass) =====================
    {
        const int mt = wid >> 1;
        const int h  = wid & 1;
        const int im = mt * 16;
        const uint32_t aRowB = (uint32_t)((im + (lane & 15)) * 256);
        uint32_t bRowG[5];
#pragma unroll
        for (int g = 0; g < 5; g++)
            bRowG[g] = (uint32_t)((im + 80 * h + 16 * g + ((lane >> 4) << 3) + (lane & 7)) * 256);

        float acc[10][4];
#pragma unroll
        for (int n = 0; n < 10; n++)
#pragma unroll
            for (int e = 0; e < 4; e++) acc[n][e] = 0.f;

#pragma unroll
        for (int st = 0; st < 8; st++) {
            uint32_t kc = 2u * (uint32_t)st;
            uint32_t aoff = ((kc + aC2) ^ rx) << 4;
            uint32_t boff = ((kc + bC2) ^ rx) << 4;
            uint32_t a0,a1,a2,a3;
            ldsm4(sb + OQ + aRowB + aoff, a0,a1,a2,a3);
#pragma unroll
            for (int g = 0; g < 5; g++) {
                uint32_t b0,b1,b2,b3;
                ldsm4(sb + OPH + bRowG[g] + boff, b0,b1,b2,b3);
                mma16816(acc[2*g    ], a0,a1,a2,a3, b0,b1);
                mma16816(acc[2*g + 1], a0,a1,a2,a3, b2,b3);
            }
        }
        __syncthreads();   // all panel reads done before zs overlay is written

        // ---- scatter (pure assignment): zs[im+r, j-r] = D[r, j] ----
#pragma unroll
        for (int nf = 0; nf < 10; nf++)
#pragma unroll
            for (int e = 0; e < 4; e++) {
                int r = er + ((e & 2) ? 8 : 0);
                int j = 80 * h + nf * 8 + ec + (e & 1);
                int tau = j - r;
                if ((unsigned)tau < 128u)
                    zs[(im + r) * ZSTRIDE + tau] = acc[nf][e];
            }
    }
    __syncthreads();

    // ===================== bias GEMM (single pass) + fused epilogue =====================
    {
        const int wr = wid >> 2;            // 0..3
        const int wc = wid & 3;             // 0..3
        uint32_t aRow[2], bRow[2];
#pragma unroll
        for (int mt = 0; mt < 2; mt++)
            aRow[mt] = (uint32_t)((wr * 32 + mt * 16 + (lane & 15)) * 256);
#pragma unroll
        for (int p = 0; p < 2; p++)
            bRow[p] = (uint32_t)((wc * 32 + p * 16 + ((lane >> 4) << 3) + (lane & 7)) * 256);

        float acc[2][4][4];
#pragma unroll
        for (int m = 0; m < 2; m++)
#pragma unroll
            for (int n = 0; n < 4; n++)
#pragma unroll
                for (int e = 0; e < 4; e++) acc[m][n][e] = 0.f;

#pragma unroll
        for (int st = 0; st < 8; st++) {
            uint32_t kc = 2u * (uint32_t)st;
            uint32_t aoff = ((kc + aC2) ^ rx) << 4;
            uint32_t boff = ((kc + bC2) ^ rx) << 4;
            uint32_t a0,a1,a2,a3,a4,a5,a6,a7;
            uint32_t b0,b1,b2,b3,b4,b5,b6,b7;
            ldsm4(sb + OQ + aRow[0] + aoff, a0,a1,a2,a3);
            ldsm4(sb + OQ + aRow[1] + aoff, a4,a5,a6,a7);
            ldsm4(sb + OBH + bRow[0] + boff, b0,b1,b2,b3);
            ldsm4(sb + OBH + bRow[1] + boff, b4,b5,b6,b7);
            mma16816(acc[0][0], a0,a1,a2,a3, b0,b1);
            mma16816(acc[0][1], a0,a1,a2,a3, b2,b3);
            mma16816(acc[0][2], a0,a1,a2,a3, b4,b5);
            mma16816(acc[0][3], a0,a1,a2,a3, b6,b7);
            mma16816(acc[1][0], a4,a5,a6,a7, b0,b1);
            mma16816(acc[1][1], a4,a5,a6,a7, b2,b3);
            mma16816(acc[1][2], a4,a5,a6,a7, b4,b5);
            mma16816(acc[1][3], a4,a5,a6,a7, b6,b7);
        }

        // ---- epilogue: Z = zs + PB, direct STG ----
#pragma unroll
        for (int mt = 0; mt < 2; mt++)
#pragma unroll
            for (int nt = 0; nt < 4; nt++) {
                int i0  = wr * 32 + mt * 16 + er;
                int tau = wc * 32 + nt * 8 + ec;
                const float* z0 = zs + i0 * ZSTRIDE + tau;
                const float* z1 = zs + (i0 + 8) * ZSTRIDE + tau;
                *reinterpret_cast<float2*>(Zb + (size_t)i0 * TDIM + tau) =
                    make_float2(acc[mt][nt][0] + z0[0], acc[mt][nt][1] + z0[1]);
                *reinterpret_cast<float2*>(Zb + (size_t)(i0 + 8) * TDIM + tau) =
                    make_float2(acc[mt][nt][2] + z1[0], acc[mt][nt][3] + z1[1]);
            }
    }
}

extern "C" void kernel_launch(void* const* d_in, const int* in_sizes, int n_in,
                              void* d_out, int out_size)
{
    const float* Q    = (const float*)d_in[0];   // (16, 1024, 128)
    const float* Km   = (const float*)d_in[1];   // (16, 2047, 128)
    const float* bias = (const float*)d_in[2];   // (1, 1, 128, 1024)
    float* Z          = (float*)d_out;           // (16, 1024, 1024)

    cudaFuncSetAttribute(sw_fused_kernel, cudaFuncAttributeMaxDynamicSharedMemorySize, SMEM_BYTES);

    cvt_qk_kernel<<<2048, 256>>>(Q, Km);
    cvt_bias_kernel<<<dim3(TDIM / 32, CDIM / 32, 1), 256>>>(bias);

    dim3 grid(TDIM / 128, TDIM / 128, 16);       // (8, 8, 16) = 1024 CTAs
    sw_fused_kernel<<<grid, NTHREADS, SMEM_BYTES>>>(Z);
}

// round 14
// speedup vs baseline: 1.1209x; 1.0226x over previous
#include <cuda_runtime.h>
#include <cuda_fp16.h>
#include <cstdint>

// Z[b,w,t] = sum_c Q[b,w,c] * ( K[b,w+t,c] + bias[c,t] ),  B=16, T=1024, C=128.
//
// Pre-pass (single kernel): Q,K -> fp16 globals; bias -> fp16 transposed g_b16[t][c].
// Main kernel: single-pass fp16 HMMA; band GEMM with 144-col window per m-tile
// (h=0: 80 cols, h=1: 64 cols - exact coverage of 0 <= tau < 128), smem-Z scatter
// overlay, bias GEMM, fused STG epilogue. Staging is pure 16B LDG->STS.

#define TDIM   1024
#define CDIM   128
#define KROWS  2047
#define NTHREADS 512

#define NQ   (16 * 1024 * 128)          // 2097152
#define NK   (16 * 2047 * 128)          // 4192256
#define NB   (1024 * 128)               // 131072

static __device__ __half g_q16[NQ];     // [b][w][c]
static __device__ __half g_k16[NK];     // [b][u][c]
static __device__ __half g_b16[NB];     // [t][c]  (transposed bias)

// ---- smem layout (bytes); fp16 buffers: rows of 256B, 16B chunks XOR-swizzled ----
#define OQ  0                            // Q fp16 (128 x 256B) = 32768
#define OPH 32768                        // K panel (256 x 256B) = 65536
#define OZS OPH                          // fp32 Z overlay (128 x 132 x 4 = 67584)
#define ZSTRIDE 132
#define OBH (OPH + 67584)                // bias B (128 x 256B) at 100352
#define SMEM_BYTES (OBH + 32768)         // 133120

__device__ __forceinline__ void ldsm4(uint32_t addr, uint32_t& r0, uint32_t& r1,
                                      uint32_t& r2, uint32_t& r3) {
    asm volatile("ldmatrix.sync.aligned.m8n8.x4.shared.b16 {%0,%1,%2,%3}, [%4];"
                 : "=r"(r0), "=r"(r1), "=r"(r2), "=r"(r3) : "r"(addr));
}
__device__ __forceinline__ void mma16816(float* d, uint32_t a0, uint32_t a1,
                                         uint32_t a2, uint32_t a3,
                                         uint32_t b0, uint32_t b1) {
    asm volatile("mma.sync.aligned.m16n8k16.row.col.f32.f16.f16.f32 "
                 "{%0,%1,%2,%3}, {%4,%5,%6,%7}, {%8,%9}, {%0,%1,%2,%3};"
                 : "+f"(d[0]), "+f"(d[1]), "+f"(d[2]), "+f"(d[3])
                 : "r"(a0), "r"(a1), "r"(a2), "r"(a3), "r"(b0), "r"(b1));
}
__device__ __forceinline__ uint32_t smem_u32(const void* p) {
    uint32_t a;
    asm("{ .reg .u64 t; cvta.to.shared.u64 t, %1; cvt.u32.u64 %0, t; }" : "=r"(a) : "l"(p));
    return a;
}
__device__ __forceinline__ uint32_t pack_h2(float x, float y) {
    __half2 h = __halves2half2(__float2half_rn(x), __float2half_rn(y));
    return *reinterpret_cast<uint32_t*>(&h);
}

// ===================== pre-pass: Q,K convert + bias transpose =====================
#define QK_BLOCKS 2048
__global__ void cvt_all_kernel(const float* __restrict__ Q,
                               const float* __restrict__ K,
                               const float* __restrict__ bias)
{
    if (blockIdx.x < QK_BLOCKS) {
        const int total = (NQ + NK) / 4;                 // float4 count
        for (int i = blockIdx.x * blockDim.x + threadIdx.x; i < total;
             i += QK_BLOCKS * blockDim.x) {
            if (i < NQ / 4) {
                float4 v = *reinterpret_cast<const float4*>(Q + 4 * (size_t)i);
                *reinterpret_cast<uint2*>(g_q16 + 4 * (size_t)i) =
                    make_uint2(pack_h2(v.x, v.y), pack_h2(v.z, v.w));
            } else {
                size_t j = (size_t)(i - NQ / 4);
                float4 v = *reinterpret_cast<const float4*>(K + 4 * j);
                *reinterpret_cast<uint2*>(g_k16 + 4 * j) =
                    make_uint2(pack_h2(v.x, v.y), pack_h2(v.z, v.w));
            }
        }
    } else {
        // bias[c][t] (128 x 1024 f32) -> g_b16[t][c]; 128 blocks of 32x32 tiles
        __shared__ float s[32][33];
        const int bb = blockIdx.x - QK_BLOCKS;           // 0..127
        const int t0 = (bb & 31) * 32;
        const int c0 = (bb >> 5) * 32;
        const int tx = threadIdx.x & 31;
        const int ty = threadIdx.x >> 5;                 // 0..7
#pragma unroll
        for (int r = 0; r < 4; r++) {
            int cc = ty + 8 * r;
            s[cc][tx] = bias[(size_t)(c0 + cc) * TDIM + t0 + tx];
        }
        __syncthreads();
#pragma unroll
        for (int r = 0; r < 4; r++) {
            int tt = ty + 8 * r;
            g_b16[(size_t)(t0 + tt) * CDIM + c0 + tx] = __float2half_rn(s[tx][tt]);
        }
    }
}

// ===================== main kernel =====================
__global__ __launch_bounds__(NTHREADS, 1)
void sw_fused_kernel(float* __restrict__ Z)
{
    extern __shared__ char smem[];
    const uint32_t sb = smem_u32(smem);
    float* zs = reinterpret_cast<float*>(smem + OZS);

    const int tid  = threadIdx.x;
    const int wid  = tid >> 5;
    const int lane = tid & 31;

    const int b  = blockIdx.z;
    const int w0 = blockIdx.y * 128;
    const int t0 = blockIdx.x * 128;
    const int u0 = w0 + t0;

    float* Zb = Z + ((size_t)b * TDIM + w0) * TDIM + t0;

    const uint32_t rx  = lane & 7;
    const uint32_t aC2 = lane >> 4;
    const uint32_t bC2 = (lane >> 3) & 1;
    const int er = lane >> 2;
    const int ec = (lane & 3) * 2;

    // ---- stage Q: 2048 x 16B chunks ----
#pragma unroll
    for (int r = 0; r < 4; r++) {
        int idx = tid + NTHREADS * r;
        int row = idx >> 4, c2 = idx & 15;
        uint4 v = *reinterpret_cast<const uint4*>(
            g_q16 + ((size_t)(b * TDIM + w0 + row)) * CDIM + c2 * 8);
        *reinterpret_cast<uint4*>(smem + OQ + row * 256 + ((c2 ^ (row & 7)) << 4)) = v;
    }
    // ---- stage K panel: 256 rows x 16 chunks = 4096 (exact) ----
#pragma unroll
    for (int r = 0; r < 8; r++) {
        int idx = tid + NTHREADS * r;
        int row = idx >> 4, c2 = idx & 15;
        int u = u0 + row;
        if (u > 2046) u = 2046;                  // only last row of last tile; discarded taus
        uint4 v = *reinterpret_cast<const uint4*>(
            g_k16 + ((size_t)(b * KROWS + u)) * CDIM + c2 * 8);
        *reinterpret_cast<uint4*>(smem + OPH + row * 256 + ((c2 ^ (row & 7)) << 4)) = v;
    }
    // ---- stage bias: 2048 x 16B chunks (already transposed) ----
#pragma unroll
    for (int r = 0; r < 4; r++) {
        int idx = tid + NTHREADS * r;
        int row = idx >> 4, c2 = idx & 15;       // row = tau
        uint4 v = *reinterpret_cast<const uint4*>(
            g_b16 + ((size_t)(t0 + row)) * CDIM + c2 * 8);
        *reinterpret_cast<uint4*>(smem + OBH + row * 256 + ((c2 ^ (row & 7)) << 4)) = v;
    }
    __syncthreads();

    // ===================== band GEMM (144-col window) =====================
    {
        const int mt = wid >> 1;
        const int h  = wid & 1;                  // h=0: groups 0..4; h=1: groups 0..3
        const int im = mt * 16;
        const uint32_t aRowB = (uint32_t)((im + (lane & 15)) * 256);
        uint32_t bRowG[5];
#pragma unroll
        for (int g = 0; g < 5; g++)
            bRowG[g] = (uint32_t)((im + 80 * h + 16 * g + ((lane >> 4) << 3) + (lane & 7)) * 256);

        float acc[10][4];
#pragma unroll
        for (int n = 0; n < 10; n++)
#pragma unroll
            for (int e = 0; e < 4; e++) acc[n][e] = 0.f;

#pragma unroll
        for (int st = 0; st < 8; st++) {
            uint32_t kc = 2u * (uint32_t)st;
            uint32_t aoff = ((kc + aC2) ^ rx) << 4;
            uint32_t boff = ((kc + bC2) ^ rx) << 4;
            uint32_t a0,a1,a2,a3;
            ldsm4(sb + OQ + aRowB + aoff, a0,a1,a2,a3);
#pragma unroll
            for (int g = 0; g < 4; g++) {        // groups 0..3 always
                uint32_t b0,b1,b2,b3;
                ldsm4(sb + OPH + bRowG[g] + boff, b0,b1,b2,b3);
                mma16816(acc[2*g    ], a0,a1,a2,a3, b0,b1);
                mma16816(acc[2*g + 1], a0,a1,a2,a3, b2,b3);
            }
            if (h == 0) {                        // group 4 only for the low half
                uint32_t b0,b1,b2,b3;
                ldsm4(sb + OPH + bRowG[4] + boff, b0,b1,b2,b3);
                mma16816(acc[8], a0,a1,a2,a3, b0,b1);
                mma16816(acc[9], a0,a1,a2,a3, b2,b3);
            }
        }
        __syncthreads();   // all panel reads done before zs overlay is written

        // ---- scatter (pure assignment): zs[im+r, j-r] = D[r, j] ----
        const int nfmax = (h == 0) ? 10 : 8;
#pragma unroll
        for (int nf = 0; nf < 10; nf++) {
            if (nf < nfmax) {
#pragma unroll
                for (int e = 0; e < 4; e++) {
                    int r = er + ((e & 2) ? 8 : 0);
                    int j = 80 * h + nf * 8 + ec + (e & 1);
                    int tau = j - r;
                    if ((unsigned)tau < 128u)
                        zs[(im + r) * ZSTRIDE + tau] = acc[nf][e];
                }
            }
        }
    }
    __syncthreads();

    // ===================== bias GEMM (single pass) + fused epilogue =====================
    {
        const int wr = wid >> 2;            // 0..3
        const int wc = wid & 3;             // 0..3
        uint32_t aRow[2], bRow[2];
#pragma unroll
        for (int mt = 0; mt < 2; mt++)
            aRow[mt] = (uint32_t)((wr * 32 + mt * 16 + (lane & 15)) * 256);
#pragma unroll
        for (int p = 0; p < 2; p++)
            bRow[p] = (uint32_t)((wc * 32 + p * 16 + ((lane >> 4) << 3) + (lane & 7)) * 256);

        float acc[2][4][4];
#pragma unroll
        for (int m = 0; m < 2; m++)
#pragma unroll
            for (int n = 0; n < 4; n++)
#pragma unroll
                for (int e = 0; e < 4; e++) acc[m][n][e] = 0.f;

#pragma unroll
        for (int st = 0; st < 8; st++) {
            uint32_t kc = 2u * (uint32_t)st;
            uint32_t aoff = ((kc + aC2) ^ rx) << 4;
            uint32_t boff = ((kc + bC2) ^ rx) << 4;
            uint32_t a0,a1,a2,a3,a4,a5,a6,a7;
            uint32_t b0,b1,b2,b3,b4,b5,b6,b7;
            ldsm4(sb + OQ + aRow[0] + aoff, a0,a1,a2,a3);
            ldsm4(sb + OQ + aRow[1] + aoff, a4,a5,a6,a7);
            ldsm4(sb + OBH + bRow[0] + boff, b0,b1,b2,b3);
            ldsm4(sb + OBH + bRow[1] + boff, b4,b5,b6,b7);
            mma16816(acc[0][0], a0,a1,a2,a3, b0,b1);
            mma16816(acc[0][1], a0,a1,a2,a3, b2,b3);
            mma16816(acc[0][2], a0,a1,a2,a3, b4,b5);
            mma16816(acc[0][3], a0,a1,a2,a3, b6,b7);
            mma16816(acc[1][0], a4,a5,a6,a7, b0,b1);
            mma16816(acc[1][1], a4,a5,a6,a7, b2,b3);
            mma16816(acc[1][2], a4,a5,a6,a7, b4,b5);
            mma16816(acc[1][3], a4,a5,a6,a7, b6,b7);
        }

        // ---- epilogue: Z = zs + PB, direct STG ----
#pragma unroll
        for (int mt = 0; mt < 2; mt++)
#pragma unroll
            for (int nt = 0; nt < 4; nt++) {
                int i0  = wr * 32 + mt * 16 + er;
                int tau = wc * 32 + nt * 8 + ec;
                const float* z0 = zs + i0 * ZSTRIDE + tau;
                const float* z1 = zs + (i0 + 8) * ZSTRIDE + tau;
                *reinterpret_cast<float2*>(Zb + (size_t)i0 * TDIM + tau) =
                    make_float2(acc[mt][nt][0] + z0[0], acc[mt][nt][1] + z0[1]);
                *reinterpret_cast<float2*>(Zb + (size_t)(i0 + 8) * TDIM + tau) =
                    make_float2(acc[mt][nt][2] + z1[0], acc[mt][nt][3] + z1[1]);
            }
    }
}

extern "C" void kernel_launch(void* const* d_in, const int* in_sizes, int n_in,
                              void* d_out, int out_size)
{
    const float* Q    = (const float*)d_in[0];   // (16, 1024, 128)
    const float* Km   = (const float*)d_in[1];   // (16, 2047, 128)
    const float* bias = (const float*)d_in[2];   // (1, 1, 128, 1024)
    float* Z          = (float*)d_out;           // (16, 1024, 1024)

    cudaFuncSetAttribute(sw_fused_kernel, cudaFuncAttributeMaxDynamicSharedMemorySize, SMEM_BYTES);

    cvt_all_kernel<<<QK_BLOCKS + 128, 256>>>(Q, Km, bias);

    dim3 grid(TDIM / 128, TDIM / 128, 16);       // (8, 8, 16) = 1024 CTAs
    sw_fused_kernel<<<grid, NTHREADS, SMEM_BYTES>>>(Z);
}

// round 15
// speedup vs baseline: 1.2053x; 1.0753x over previous
#include <cuda_runtime.h>
#include <cuda_fp16.h>
#include <cstdint>

// Z[b,w,t] = sum_c Q[b,w,c] * ( K[b,w+t,c] + bias[c,t] ),  B=16, T=1024, C=128.
//
// Pre-pass: Q,K -> fp16 globals; bias -> fp16 transposed g_b16[t][c]. (MLP-2 convert)
// Main kernel (warp-specialized): warps 0-7 = band GEMM (m=32 tiles, 160-col window),
// warps 8-15 = bias GEMM (16 rows x 128 cols each), CONCURRENT. Band warps bar.sync(1)
// then scatter to smem zs (overlay on panel); full sync; bias warps run fused epilogue.

#define TDIM   1024
#define CDIM   128
#define KROWS  2047
#define NTHREADS 512

#define NQ   (16 * 1024 * 128)          // 2097152
#define NK   (16 * 2047 * 128)          // 4192256
#define NB   (1024 * 128)               // 131072

static __device__ __half g_q16[NQ];     // [b][w][c]
static __device__ __half g_k16[NK];     // [b][u][c]
static __device__ __half g_b16[NB];     // [t][c]  (transposed bias)

// ---- smem layout (bytes); fp16 buffers: rows of 256B, 16B chunks XOR-swizzled ----
#define OQ  0                            // Q fp16 (128 x 256B) = 32768
#define OPH 32768                        // K panel (256 x 256B) = 65536
#define OZS OPH                          // fp32 Z overlay (128 x 132 x 4 = 67584)
#define ZSTRIDE 132
#define OBH (OPH + 67584)                // bias B (128 x 256B) at 100352
#define SMEM_BYTES (OBH + 32768)         // 133120

__device__ __forceinline__ void ldsm4(uint32_t addr, uint32_t& r0, uint32_t& r1,
                                      uint32_t& r2, uint32_t& r3) {
    asm volatile("ldmatrix.sync.aligned.m8n8.x4.shared.b16 {%0,%1,%2,%3}, [%4];"
                 : "=r"(r0), "=r"(r1), "=r"(r2), "=r"(r3) : "r"(addr));
}
__device__ __forceinline__ void mma16816(float* d, uint32_t a0, uint32_t a1,
                                         uint32_t a2, uint32_t a3,
                                         uint32_t b0, uint32_t b1) {
    asm volatile("mma.sync.aligned.m16n8k16.row.col.f32.f16.f16.f32 "
                 "{%0,%1,%2,%3}, {%4,%5,%6,%7}, {%8,%9}, {%0,%1,%2,%3};"
                 : "+f"(d[0]), "+f"(d[1]), "+f"(d[2]), "+f"(d[3])
                 : "r"(a0), "r"(a1), "r"(a2), "r"(a3), "r"(b0), "r"(b1));
}
__device__ __forceinline__ uint32_t smem_u32(const void* p) {
    uint32_t a;
    asm("{ .reg .u64 t; cvta.to.shared.u64 t, %1; cvt.u32.u64 %0, t; }" : "=r"(a) : "l"(p));
    return a;
}
__device__ __forceinline__ uint32_t pack_h2(float x, float y) {
    __half2 h = __halves2half2(__float2half_rn(x), __float2half_rn(y));
    return *reinterpret_cast<uint32_t*>(&h);
}

// ===================== pre-pass: Q,K convert (MLP 2) + bias transpose =====================
#define QK_BLOCKS 3071                   // 3071*256 threads x 2 float4 = (NQ+NK)/4 exactly
__global__ void cvt_all_kernel(const float* __restrict__ Q,
                               const float* __restrict__ K,
                               const float* __restrict__ bias)
{
    if (blockIdx.x < QK_BLOCKS) {
        const int half = QK_BLOCKS * 256;                // 786176
        int i0 = blockIdx.x * 256 + threadIdx.x;
#pragma unroll
        for (int p = 0; p < 2; p++) {
            int i = i0 + p * half;
            if (i < NQ / 4) {
                float4 v = *reinterpret_cast<const float4*>(Q + 4 * (size_t)i);
                *reinterpret_cast<uint2*>(g_q16 + 4 * (size_t)i) =
                    make_uint2(pack_h2(v.x, v.y), pack_h2(v.z, v.w));
            } else {
                size_t j = (size_t)(i - NQ / 4);
                float4 v = *reinterpret_cast<const float4*>(K + 4 * j);
                *reinterpret_cast<uint2*>(g_k16 + 4 * j) =
                    make_uint2(pack_h2(v.x, v.y), pack_h2(v.z, v.w));
            }
        }
    } else {
        // bias[c][t] (128 x 1024 f32) -> g_b16[t][c]; 128 blocks of 32x32 tiles
        __shared__ float s[32][33];
        const int bb = blockIdx.x - QK_BLOCKS;           // 0..127
        const int t0 = (bb & 31) * 32;
        const int c0 = (bb >> 5) * 32;
        const int tx = threadIdx.x & 31;
        const int ty = threadIdx.x >> 5;                 // 0..7
#pragma unroll
        for (int r = 0; r < 4; r++) {
            int cc = ty + 8 * r;
            s[cc][tx] = bias[(size_t)(c0 + cc) * TDIM + t0 + tx];
        }
        __syncthreads();
#pragma unroll
        for (int r = 0; r < 4; r++) {
            int tt = ty + 8 * r;
            g_b16[(size_t)(t0 + tt) * CDIM + c0 + tx] = __float2half_rn(s[tx][tt]);
        }
    }
}

// ===================== main kernel =====================
__global__ __launch_bounds__(NTHREADS, 1)
void sw_fused_kernel(float* __restrict__ Z)
{
    extern __shared__ char smem[];
    const uint32_t sb = smem_u32(smem);
    float* zs = reinterpret_cast<float*>(smem + OZS);

    const int tid  = threadIdx.x;
    const int wid  = tid >> 5;
    const int lane = tid & 31;

    const int b  = blockIdx.z;
    const int w0 = blockIdx.y * 128;
    const int t0 = blockIdx.x * 128;
    const int u0 = w0 + t0;

    float* Zb = Z + ((size_t)b * TDIM + w0) * TDIM + t0;

    const uint32_t rx  = lane & 7;
    const uint32_t aC2 = lane >> 4;
    const uint32_t bC2 = (lane >> 3) & 1;
    const int er = lane >> 2;
    const int ec = (lane & 3) * 2;

    // ---- stage Q: 2048 x 16B chunks ----
#pragma unroll
    for (int r = 0; r < 4; r++) {
        int idx = tid + NTHREADS * r;
        int row = idx >> 4, c2 = idx & 15;
        uint4 v = *reinterpret_cast<const uint4*>(
            g_q16 + ((size_t)(b * TDIM + w0 + row)) * CDIM + c2 * 8);
        *reinterpret_cast<uint4*>(smem + OQ + row * 256 + ((c2 ^ (row & 7)) << 4)) = v;
    }
    // ---- stage K panel: 256 rows x 16 chunks = 4096 (exact) ----
#pragma unroll
    for (int r = 0; r < 8; r++) {
        int idx = tid + NTHREADS * r;
        int row = idx >> 4, c2 = idx & 15;
        int u = u0 + row;
        if (u > 2046) u = 2046;                  // only last row of last tile; discarded taus
        uint4 v = *reinterpret_cast<const uint4*>(
            g_k16 + ((size_t)(b * KROWS + u)) * CDIM + c2 * 8);
        *reinterpret_cast<uint4*>(smem + OPH + row * 256 + ((c2 ^ (row & 7)) << 4)) = v;
    }
    // ---- stage bias: 2048 x 16B chunks (already transposed) ----
#pragma unroll
    for (int r = 0; r < 4; r++) {
        int idx = tid + NTHREADS * r;
        int row = idx >> 4, c2 = idx & 15;       // row = tau
        uint4 v = *reinterpret_cast<const uint4*>(
            g_b16 + ((size_t)(t0 + row)) * CDIM + c2 * 8);
        *reinterpret_cast<uint4*>(smem + OBH + row * 256 + ((c2 ^ (row & 7)) << 4)) = v;
    }
    __syncthreads();

    if (wid < 8) {
        // ===================== band GEMM: warps 0-7, m=32 tiles =====================
        const int mt = wid >> 1;                 // 0..3, rows [32mt, 32mt+32)
        const int h  = wid & 1;                  // cols [80h, 80h+80)
        const int im = mt * 32;
        uint32_t aRowB[2];
#pragma unroll
        for (int mf = 0; mf < 2; mf++)
            aRowB[mf] = (uint32_t)((im + 16 * mf + (lane & 15)) * 256);
        uint32_t bRowG[5];
#pragma unroll
        for (int g = 0; g < 5; g++)
            bRowG[g] = (uint32_t)((im + 80 * h + 16 * g + ((lane >> 4) << 3) + (lane & 7)) * 256);

        float acc[2][10][4];                     // [mfrag][nfrag][elem]
#pragma unroll
        for (int m = 0; m < 2; m++)
#pragma unroll
            for (int n = 0; n < 10; n++)
#pragma unroll
                for (int e = 0; e < 4; e++) acc[m][n][e] = 0.f;

#pragma unroll
        for (int st = 0; st < 8; st++) {
            uint32_t kc = 2u * (uint32_t)st;
            uint32_t aoff = ((kc + aC2) ^ rx) << 4;
            uint32_t boff = ((kc + bC2) ^ rx) << 4;
            uint32_t a0,a1,a2,a3,a4,a5,a6,a7;
            ldsm4(sb + OQ + aRowB[0] + aoff, a0,a1,a2,a3);
            ldsm4(sb + OQ + aRowB[1] + aoff, a4,a5,a6,a7);
#pragma unroll
            for (int g = 0; g < 5; g++) {
                uint32_t b0,b1,b2,b3;
                ldsm4(sb + OPH + bRowG[g] + boff, b0,b1,b2,b3);
                mma16816(acc[0][2*g    ], a0,a1,a2,a3, b0,b1);
                mma16816(acc[0][2*g + 1], a0,a1,a2,a3, b2,b3);
                mma16816(acc[1][2*g    ], a4,a5,a6,a7, b0,b1);
                mma16816(acc[1][2*g + 1], a4,a5,a6,a7, b2,b3);
            }
        }
        // band warps only: all panel reads done before zs overlay is written
        asm volatile("bar.sync 1, 256;" ::: "memory");

        // ---- scatter (pure assignment): zs[im+r, j-r] = D[r, j] ----
#pragma unroll
        for (int mf = 0; mf < 2; mf++)
#pragma unroll
            for (int nf = 0; nf < 10; nf++)
#pragma unroll
                for (int e = 0; e < 4; e++) {
                    int r = 16 * mf + er + ((e & 2) ? 8 : 0);
                    int j = 80 * h + nf * 8 + ec + (e & 1);
                    int tau = j - r;
                    if ((unsigned)tau < 128u)
                        zs[(im + r) * ZSTRIDE + tau] = acc[mf][nf][e];
                }
        __syncthreads();
    } else {
        // ===================== bias GEMM: warps 8-15, 16 rows x 128 cols =====================
        const int wr = wid - 8;                  // 0..7, rows [16wr, 16wr+16)
        const uint32_t aRow = (uint32_t)((wr * 16 + (lane & 15)) * 256);
        uint32_t bRow[8];
#pragma unroll
        for (int p = 0; p < 8; p++)
            bRow[p] = (uint32_t)((16 * p + ((lane >> 4) << 3) + (lane & 7)) * 256);

        float acc[16][4];
#pragma unroll
        for (int n = 0; n < 16; n++)
#pragma unroll
            for (int e = 0; e < 4; e++) acc[n][e] = 0.f;

#pragma unroll
        for (int st = 0; st < 8; st++) {
            uint32_t kc = 2u * (uint32_t)st;
            uint32_t aoff = ((kc + aC2) ^ rx) << 4;
            uint32_t boff = ((kc + bC2) ^ rx) << 4;
            uint32_t a0,a1,a2,a3;
            ldsm4(sb + OQ + aRow + aoff, a0,a1,a2,a3);
#pragma unroll
            for (int p = 0; p < 8; p++) {
                uint32_t b0,b1,b2,b3;
                ldsm4(sb + OBH + bRow[p] + boff, b0,b1,b2,b3);
                mma16816(acc[2*p    ], a0,a1,a2,a3, b0,b1);
                mma16816(acc[2*p + 1], a0,a1,a2,a3, b2,b3);
            }
        }
        __syncthreads();   // wait for band scatter to land in zs

        // ---- fused epilogue: Z = zs + PB, direct STG ----
        const int i0 = wr * 16 + er;
#pragma unroll
        for (int nf = 0; nf < 16; nf++) {
            int tau = nf * 8 + ec;
            const float* z0 = zs + i0 * ZSTRIDE + tau;
            const float* z1 = zs + (i0 + 8) * ZSTRIDE + tau;
            *reinterpret_cast<float2*>(Zb + (size_t)i0 * TDIM + tau) =
                make_float2(acc[nf][0] + z0[0], acc[nf][1] + z0[1]);
            *reinterpret_cast<float2*>(Zb + (size_t)(i0 + 8) * TDIM + tau) =
                make_float2(acc[nf][2] + z1[0], acc[nf][3] + z1[1]);
        }
    }
}

extern "C" void kernel_launch(void* const* d_in, const int* in_sizes, int n_in,
                              void* d_out, int out_size)
{
    const float* Q    = (const float*)d_in[0];   // (16, 1024, 128)
    const float* Km   = (const float*)d_in[1];   // (16, 2047, 128)
    const float* bias = (const float*)d_in[2];   // (1, 1, 128, 1024)
    float* Z          = (float*)d_out;           // (16, 1024, 1024)

    cudaFuncSetAttribute(sw_fused_kernel, cudaFuncAttributeMaxDynamicSharedMemorySize, SMEM_BYTES);

    cvt_all_kernel<<<QK_BLOCKS + 128, 256>>>(Q, Km, bias);

    dim3 grid(TDIM / 128, TDIM / 128, 16);       // (8, 8, 16) = 1024 CTAs
    sw_fused_kernel<<<grid, NTHREADS, SMEM_BYTES>>>(Z);
}